// round 6
// baseline (speedup 1.0000x reference)
#include <cuda_runtime.h>
#include <cuda_fp16.h>

#define NMAX 100000
#define EMAX 640000
#define CH   128
#define CH4  32
#define MBLK 128
#define LDX  36
#define LDW  136
#define NBLK_SCAN 98
#define FLAG_A (1 << 30)
#define FLAG_P (2 << 30)
#define VALMASK ((1 << 30) - 1)

// GEMM dynamic smem: W full (128*LDW) + 2 X buffers (128*LDX each), in 4B words
#define GEMM_SMEM_WORDS (128 * LDW + 2 * 128 * LDX)
#define GEMM_SMEM_BYTES (GEMM_SMEM_WORDS * 4)

// ---------------- scratch (static device globals; no allocation) ----------------
__device__ float g_deg[NMAX];
__device__ float g_D[NMAX];
__device__ int   g_cnt[NMAX];
__device__ int   g_rowptr[NMAX + 1];
__device__ int   g_cursor[NMAX];
__device__ int2  g_edge[EMAX];           // (col, val-as-int), D folded into val
__device__ __half g_Yh[(size_t)NMAX * CH];
__device__ int   g_state[128];           // lookback scan states

// ---------------- prep kernels ----------------
__global__ void k_deg(const int* __restrict__ row, const float* __restrict__ vals, int E) {
    int i = (blockIdx.x * blockDim.x + threadIdx.x) * 2;
    if (i + 1 < E) {
        int2   r2 = *(const int2*)&row[i];
        float2 v2 = *(const float2*)&vals[i];
        atomicAdd(&g_deg[r2.x], v2.x);
        atomicAdd(&g_cnt[r2.x], 1);
        atomicAdd(&g_deg[r2.y], v2.y);
        atomicAdd(&g_cnt[r2.y], 1);
    } else if (i < E) {
        int r = row[i];
        atomicAdd(&g_deg[r], vals[i]);
        atomicAdd(&g_cnt[r], 1);
    }
}

// single-pass scan with decoupled lookback: writes rowptr, cursor, D.
// 256 threads x 4 elems = 1024 per block.
__global__ void k_scanB(int N) {
    __shared__ int ws[8];
    __shared__ int sprefix;
    int t = threadIdx.x;
    int lane = t & 31, wid = t >> 5;
    int b = blockIdx.x;
    int i0 = b * 1024 + t * 4;

    int4 c4;
    if (i0 + 3 < N) c4 = *(const int4*)&g_cnt[i0];
    else {
        c4.x = (i0 + 0 < N) ? g_cnt[i0 + 0] : 0;
        c4.y = (i0 + 1 < N) ? g_cnt[i0 + 1] : 0;
        c4.z = (i0 + 2 < N) ? g_cnt[i0 + 2] : 0;
        c4.w = (i0 + 3 < N) ? g_cnt[i0 + 3] : 0;
    }
    int p0 = c4.x, p1 = p0 + c4.y, p2 = p1 + c4.z, p3 = p2 + c4.w;
    int x = p3;
#pragma unroll
    for (int o = 1; o < 32; o <<= 1) {
        int y = __shfl_up_sync(0xFFFFFFFFu, x, o);
        if (lane >= o) x += y;
    }
    if (lane == 31) ws[wid] = x;
    __syncthreads();
    if (t < 32) {
        int wv = (t < 8) ? ws[t] : 0;
#pragma unroll
        for (int o = 1; o < 8; o <<= 1) {
            int y = __shfl_up_sync(0xFFFFFFFFu, wv, o);
            if (lane >= o) wv += y;
        }
        if (t < 8) ws[t] = wv;
    }
    __syncthreads();
    int total = ws[7];
    int texcl = ((wid > 0) ? ws[wid - 1] : 0) + x - p3;

    // lookback (thread 0 only)
    if (t == 0) {
        if (b == 0) {
            *(volatile int*)&g_state[0] = FLAG_P | total;
            sprefix = 0;
        } else {
            *(volatile int*)&g_state[b] = FLAG_A | total;
            int run = 0, j = b - 1;
            while (true) {
                int s;
                do { s = *(volatile int*)&g_state[j]; } while ((s & (FLAG_A | FLAG_P)) == 0);
                run += (s & VALMASK);
                if (s & FLAG_P) break;
                j--;
            }
            sprefix = run;
            *(volatile int*)&g_state[b] = FLAG_P | (run + total);
        }
    }
    __syncthreads();
    int pre = sprefix;

    int e0 = pre + texcl;
    if (i0 + 0 < N) { g_rowptr[i0 + 1] = e0 + p0; g_cursor[i0 + 0] = e0 + p0 - c4.x; }
    if (i0 + 1 < N) { g_rowptr[i0 + 2] = e0 + p1; g_cursor[i0 + 1] = e0 + p1 - c4.y; }
    if (i0 + 2 < N) { g_rowptr[i0 + 3] = e0 + p2; g_cursor[i0 + 2] = e0 + p2 - c4.z; }
    if (i0 + 3 < N) { g_rowptr[i0 + 4] = e0 + p3; g_cursor[i0 + 3] = e0 + p3 - c4.w; }
    if (b == 0 && t == 0) g_rowptr[0] = 0;

    // D = rsqrt(deg + 1)
    if (i0 + 3 < N) {
        float4 dg = *(const float4*)&g_deg[i0];
        float4 dd = make_float4(rsqrtf(dg.x + 1.f), rsqrtf(dg.y + 1.f),
                                rsqrtf(dg.z + 1.f), rsqrtf(dg.w + 1.f));
        *(float4*)&g_D[i0] = dd;
    } else {
#pragma unroll
        for (int k = 0; k < 4; k++)
            if (i0 + k < N) g_D[i0 + k] = rsqrtf(g_deg[i0 + k] + 1.f);
    }
}

__global__ void k_fill(const int* __restrict__ row, const int* __restrict__ col,
                       const float* __restrict__ vals, int E) {
    int i = (blockIdx.x * blockDim.x + threadIdx.x) * 2;
    if (i + 1 < E) {
        int2   r2 = *(const int2*)&row[i];
        int2   c2 = *(const int2*)&col[i];
        float2 v2 = *(const float2*)&vals[i];
        float  e0 = v2.x * __ldg(&g_D[c2.x]);
        float  e1 = v2.y * __ldg(&g_D[c2.y]);
        int p0 = atomicAdd(&g_cursor[r2.x], 1);
        g_edge[p0] = make_int2(c2.x, __float_as_int(e0));
        int p1 = atomicAdd(&g_cursor[r2.y], 1);
        g_edge[p1] = make_int2(c2.y, __float_as_int(e1));
    } else if (i < E) {
        int c = col[i];
        float ev = vals[i] * __ldg(&g_D[c]);
        int p = atomicAdd(&g_cursor[row[i]], 1);
        g_edge[p] = make_int2(c, __float_as_int(ev));
    }
}

// tail reset (overlaps k_agg on the other stream)
__global__ void k_reset(int N) {
    int i = blockIdx.x * blockDim.x + threadIdx.x;
    int i4 = i * 4;
    if (i4 + 3 < N) {
        *(float4*)&g_deg[i4] = make_float4(0.f, 0.f, 0.f, 0.f);
        *(int4*)&g_cnt[i4] = make_int4(0, 0, 0, 0);
    } else {
        for (int k = 0; k < 4; k++)
            if (i4 + k < N) { g_deg[i4 + k] = 0.f; g_cnt[i4 + k] = 0; }
    }
    if (i < 128) g_state[i] = 0;
}

// ---------------- GEMM (tf32 mma, cp.async pipelined): Yh = fp16(X @ W) ----------------
__device__ __forceinline__ void cpa16(unsigned saddr, const void* gptr, int szbytes) {
    asm volatile("cp.async.ca.shared.global [%0], [%1], 16, %2;"
                 :: "r"(saddr), "l"(gptr), "r"(szbytes));
}
__device__ __forceinline__ unsigned rnd(unsigned u) { return u + 0x1000u; }  // fp32->tf32 RN

__global__ __launch_bounds__(256, 2) void k_gemm_tc(const float* __restrict__ X,
                                                    const float* __restrict__ W, int N) {
    extern __shared__ __align__(16) unsigned smem_dyn[];
    unsigned* Ws = smem_dyn;                       // 128 x LDW (full K resident)
    unsigned* Xs = smem_dyn + 128 * LDW;           // 2 x (128 x LDX)

    int tid = threadIdx.x;
    int lane = tid & 31;
    int w = tid >> 5;
    int g = lane >> 2;
    int t = lane & 3;
    int mbase = (w >> 1) * 32;
    int nbase = (w & 1) * 64;
    int row0 = blockIdx.x * MBLK;

    unsigned sWs = (unsigned)__cvta_generic_to_shared(Ws);
    unsigned sXs = (unsigned)__cvta_generic_to_shared(Xs);

    const float4* X4 = (const float4*)X;
    const float4* W4 = (const float4*)W;

    // stage ALL of W (128 x 128 fp32): 4096 float4, 16 per thread
#pragma unroll
    for (int it = 0; it < 16; it++) {
        int idx = tid + it * 256;
        int k = idx >> 5, q = idx & 31;
        cpa16(sWs + (k * LDW + q * 4) * 4, &W4[(size_t)k * CH4 + q], 16);
    }
    // stage X tile kt=0 into buf 0: 1024 float4, 4 per thread
#pragma unroll
    for (int it = 0; it < 4; it++) {
        int idx = tid + it * 256;
        int r = idx >> 3, q = idx & 7;
        int gr = row0 + r;
        cpa16(sXs + (r * LDX + q * 4) * 4, &X4[(size_t)gr * CH4 + q], (gr < N) ? 16 : 0);
    }
    asm volatile("cp.async.commit_group;");
    // stage X tile kt=1 into buf 1
#pragma unroll
    for (int it = 0; it < 4; it++) {
        int idx = tid + it * 256;
        int r = idx >> 3, q = idx & 7;
        int gr = row0 + r;
        cpa16(sXs + (128 * LDX + r * LDX + q * 4) * 4, &X4[(size_t)gr * CH4 + 8 + q], (gr < N) ? 16 : 0);
    }
    asm volatile("cp.async.commit_group;");

    float c[2][8][4];
#pragma unroll
    for (int mi = 0; mi < 2; mi++)
#pragma unroll
        for (int ni = 0; ni < 8; ni++)
#pragma unroll
            for (int q = 0; q < 4; q++) c[mi][ni][q] = 0.f;

#pragma unroll
    for (int kt = 0; kt < 4; kt++) {
        if (kt < 3) asm volatile("cp.async.wait_group 1;");
        else        asm volatile("cp.async.wait_group 0;");
        __syncthreads();

        const unsigned* Xb = Xs + (kt & 1) * (128 * LDX);
        int krow = kt * 32;
#pragma unroll
        for (int kk = 0; kk < 32; kk += 8) {
            unsigned a[2][4];
#pragma unroll
            for (int mi = 0; mi < 2; mi++) {
                int r = mbase + mi * 16;
                a[mi][0] = rnd(Xb[(r + g) * LDX + kk + t]);
                a[mi][1] = rnd(Xb[(r + g + 8) * LDX + kk + t]);
                a[mi][2] = rnd(Xb[(r + g) * LDX + kk + t + 4]);
                a[mi][3] = rnd(Xb[(r + g + 8) * LDX + kk + t + 4]);
            }
#pragma unroll
            for (int ni = 0; ni < 8; ni++) {
                int cn = nbase + ni * 8 + g;
                unsigned b0 = rnd(Ws[(krow + kk + t) * LDW + cn]);
                unsigned b1 = rnd(Ws[(krow + kk + t + 4) * LDW + cn]);
#pragma unroll
                for (int mi = 0; mi < 2; mi++) {
                    asm volatile(
                        "mma.sync.aligned.m16n8k8.row.col.f32.tf32.tf32.f32 "
                        "{%0,%1,%2,%3}, {%4,%5,%6,%7}, {%8,%9}, {%0,%1,%2,%3};"
                        : "+f"(c[mi][ni][0]), "+f"(c[mi][ni][1]),
                          "+f"(c[mi][ni][2]), "+f"(c[mi][ni][3])
                        : "r"(a[mi][0]), "r"(a[mi][1]), "r"(a[mi][2]), "r"(a[mi][3]),
                          "r"(b0), "r"(b1));
                }
            }
        }

        if (kt < 2) {
            __syncthreads();   // buffer kt&1 consumed; safe to overwrite
#pragma unroll
            for (int it = 0; it < 4; it++) {
                int idx = tid + it * 256;
                int r = idx >> 3, q = idx & 7;
                int gr = row0 + r;
                cpa16(sXs + ((kt & 1) * 128 * LDX + r * LDX + q * 4) * 4,
                      &X4[(size_t)gr * CH4 + (kt + 2) * 8 + q], (gr < N) ? 16 : 0);
            }
            asm volatile("cp.async.commit_group;");
        }
    }

    // epilogue: Yh = fp16(acc)
#pragma unroll
    for (int mi = 0; mi < 2; mi++) {
        int r0 = row0 + mbase + mi * 16 + g;
        int r1 = r0 + 8;
#pragma unroll
        for (int ni = 0; ni < 8; ni++) {
            int cn = nbase + ni * 8 + 2 * t;
            if (r0 < N)
                *(__half2*)&g_Yh[(size_t)r0 * CH + cn] = __floats2half2_rn(c[mi][ni][0], c[mi][ni][1]);
            if (r1 < N)
                *(__half2*)&g_Yh[(size_t)r1 * CH + cn] = __floats2half2_rn(c[mi][ni][2], c[mi][ni][3]);
        }
    }
}

// ---------------- aggregation: out = D * (A' @ Yh) + bias ----------------
__global__ void k_agg(const float* __restrict__ bias, float* __restrict__ out, int N) {
    int gw = (blockIdx.x * blockDim.x + threadIdx.x) >> 5;
    int lane = threadIdx.x & 31;
    if (gw >= N) return;
    int g2 = lane >> 4;
    int sub = lane & 15;
    int s = g_rowptr[gw], e = g_rowptr[gw + 1];

    float acc[8];
#pragma unroll
    for (int j = 0; j < 8; j++) acc[j] = 0.f;

    const uint4* Y4 = (const uint4*)g_Yh;
    int i = s;
#pragma unroll 2
    for (; i + 1 < e; i += 2) {
        int2 ed = __ldg(&g_edge[i + g2]);
        float v = __int_as_float(ed.y);
        uint4 u = __ldg(&Y4[(size_t)ed.x * 16 + sub]);
        float2 f0 = __half22float2(*(__half2*)&u.x);
        float2 f1 = __half22float2(*(__half2*)&u.y);
        float2 f2 = __half22float2(*(__half2*)&u.z);
        float2 f3 = __half22float2(*(__half2*)&u.w);
        acc[0] = fmaf(v, f0.x, acc[0]);
        acc[1] = fmaf(v, f0.y, acc[1]);
        acc[2] = fmaf(v, f1.x, acc[2]);
        acc[3] = fmaf(v, f1.y, acc[3]);
        acc[4] = fmaf(v, f2.x, acc[4]);
        acc[5] = fmaf(v, f2.y, acc[5]);
        acc[6] = fmaf(v, f3.x, acc[6]);
        acc[7] = fmaf(v, f3.y, acc[7]);
    }
    if (i < e && g2 == 0) {
        int2 ed = __ldg(&g_edge[i]);
        float v = __int_as_float(ed.y);
        uint4 u = __ldg(&Y4[(size_t)ed.x * 16 + sub]);
        float2 f0 = __half22float2(*(__half2*)&u.x);
        float2 f1 = __half22float2(*(__half2*)&u.y);
        float2 f2 = __half22float2(*(__half2*)&u.z);
        float2 f3 = __half22float2(*(__half2*)&u.w);
        acc[0] = fmaf(v, f0.x, acc[0]);
        acc[1] = fmaf(v, f0.y, acc[1]);
        acc[2] = fmaf(v, f1.x, acc[2]);
        acc[3] = fmaf(v, f1.y, acc[3]);
        acc[4] = fmaf(v, f2.x, acc[4]);
        acc[5] = fmaf(v, f2.y, acc[5]);
        acc[6] = fmaf(v, f3.x, acc[6]);
        acc[7] = fmaf(v, f3.y, acc[7]);
    }
#pragma unroll
    for (int j = 0; j < 8; j++)
        acc[j] += __shfl_xor_sync(0xFFFFFFFFu, acc[j], 16);

    if (g2 == 0) {
        float d = g_D[gw];
        float4 b0 = __ldg(&((const float4*)bias)[sub * 2]);
        float4 b1 = __ldg(&((const float4*)bias)[sub * 2 + 1]);
        float4 o0 = make_float4(fmaf(d, acc[0], b0.x), fmaf(d, acc[1], b0.y),
                                fmaf(d, acc[2], b0.z), fmaf(d, acc[3], b0.w));
        float4 o1 = make_float4(fmaf(d, acc[4], b1.x), fmaf(d, acc[5], b1.y),
                                fmaf(d, acc[6], b1.z), fmaf(d, acc[7], b1.w));
        float4* op = (float4*)&out[(size_t)gw * CH + sub * 8];
        op[0] = o0;
        op[1] = o1;
    }
}

// ---------------- launch: fork/join — GEMM overlaps CSR build; reset overlaps agg ----------------
extern "C" void kernel_launch(void* const* d_in, const int* in_sizes, int n_in,
                              void* d_out, int out_size) {
    const int*   row  = (const int*)d_in[0];
    const int*   col  = (const int*)d_in[1];
    const float* vals = (const float*)d_in[2];
    const float* X    = (const float*)d_in[3];
    const float* W    = (const float*)d_in[4];
    const float* bias = (const float*)d_in[5];
    int E = in_sizes[0];
    int N = in_sizes[3] / CH;
    float* out = (float*)d_out;

    static cudaStream_t s2 = nullptr;
    static cudaEvent_t evFork = nullptr, evJoin = nullptr, evJoin2 = nullptr;
    if (s2 == nullptr) {
        cudaStreamCreateWithFlags(&s2, cudaStreamNonBlocking);
        cudaEventCreateWithFlags(&evFork, cudaEventDisableTiming);
        cudaEventCreateWithFlags(&evJoin, cudaEventDisableTiming);
        cudaEventCreateWithFlags(&evJoin2, cudaEventDisableTiming);
        cudaFuncSetAttribute(k_gemm_tc, cudaFuncAttributeMaxDynamicSharedMemorySize,
                             GEMM_SMEM_BYTES);
    }

    int nb_scan = (N + 1023) / 1024;
    int half_e  = (E + 1) / 2;

    cudaEventRecord(evFork, 0);
    cudaStreamWaitEvent(s2, evFork, 0);

    // main stream: GEMM (independent of the prep chain)
    k_gemm_tc<<<(N + MBLK - 1) / MBLK, 256, GEMM_SMEM_BYTES, 0>>>(X, W, N);

    // prep stream: CSR build + D   (globals zero-init on first run; k_reset restores)
    k_deg  <<<(half_e + 255) / 256, 256, 0, s2>>>(row, vals, E);
    k_scanB<<<nb_scan, 256, 0, s2>>>(N);
    k_fill <<<(half_e + 255) / 256, 256, 0, s2>>>(row, col, vals, E);
    cudaEventRecord(evJoin, s2);

    // tail reset on s2 — overlaps agg on stream 0
    k_reset<<<(N / 4 + 255) / 256, 256, 0, s2>>>(N);
    cudaEventRecord(evJoin2, s2);

    cudaStreamWaitEvent(0, evJoin, 0);
    k_agg<<<(N * 32 + 255) / 256, 256, 0, 0>>>(bias, out, N);
    cudaStreamWaitEvent(0, evJoin2, 0);
}